// round 15
// baseline (speedup 1.0000x reference)
#include <cuda_runtime.h>
#include <cstdint>

// Problem constants
#define B_DIM   8192
#define IN_DIM  256
#define OUT_DIM 256
#define MV      8

// GEMM: C[8192 x 512] = A[8192 x 1024] * Wmat[1024 x 512]
//   A[b][k] = x[b][k/4][comp{0,1,2,4}[k%4]]
//   col n=2i -> y0[:,i], n=2i+1 -> y4[:,i]
#define KDIM    1024
#define NNDIM   512

#define BM      128
#define BN      128
#define KC      32
#define NCHUNK  (KDIM / KC)   // 32
#define NTHR    256           // 8 warps: wm = wrp>>2 (2), wn = wrp&3 (4); warp tile 64x32

// A fragment smem layout (words): addr = kstep*1032 + (wm*4 + mt)*128 + reg*32 + lane
#define KSTRIDE  1032
#define AF_WORDS (4 * KSTRIDE)          // 4128 words per buffer
#define SM_WORDS (2 * AF_WORDS)
#define SM_BYTES (SM_WORDS * 4)          // 33024

// Wmat fragment layout: [nblk8][chunk32][kstep4][wn2][nt4][lane32][reg2]
__device__ uint32_t g_Wfrag[NNDIM * KDIM];   // 2 MB, L2-resident after warmup

__device__ __forceinline__ uint32_t f2tf32(float f) {
    uint32_t u; asm("cvt.rna.tf32.f32 %0, %1;" : "=r"(u) : "f"(f)); return u;
}

// ---- Kernel 1: build W fragments from w (256,256,8) ----
__global__ void wprep_kernel(const float* __restrict__ w)
{
    const int idx = blockIdx.x * blockDim.x + threadIdx.x;   // 524288
    const int reg   = idx & 1;
    const int lane  = (idx >> 1) & 31;
    const int nt    = (idx >> 6) & 3;
    const int wn    = (idx >> 8) & 1;
    const int kstep = (idx >> 9) & 3;
    const int chunk = (idx >> 11) & 31;
    const int nblk  = idx >> 16;
    const int n = nblk * 64 + wn * 32 + nt * 8 + (lane >> 2);
    const int k = chunk * 32 + kstep * 8 + reg * 4 + (lane & 3);
    const int j = k >> 2, s = k & 3, i = n >> 1;
    const float* wr = w + ((size_t)j * OUT_DIM + i) * MV;
    float v = 0.0f;
    if ((n & 1) == 0) {
        if (s < 3) v = wr[s];                 // y0: w0,w1,w2,0
    } else {
        if (s == 1) v = wr[2];                // y4:  x1*w2
        else if (s == 2) v = -wr[1];          //     -x2*w1
        else if (s == 3) v = wr[0];           //      x4*w0
    }
    g_Wfrag[idx] = f2tf32(v);
}

// ---- Kernel 2: tf32 mma.sync GEMM; B fragments direct from L2 ----
__global__ void __launch_bounds__(NTHR, 2)
ga_gemm_kernel(const float* __restrict__ x,
               const float* __restrict__ bias,
               float* __restrict__ out)
{
    extern __shared__ uint32_t sm[];   // AF buf0 | AF buf1

    const int tid  = threadIdx.x;
    const int lane = tid & 31;
    const int wrp  = tid >> 5;
    const int wm   = wrp >> 2;       // 0..1  (M half: 64 rows)
    const int wn   = wrp & 3;        // 0..3  (N quarter: 32 cols)
    const int nhalf = wn >> 1;       // which 64-col W block
    const int wnbit = wn & 1;
    const int bBase = blockIdx.x * BM;
    const int nblk  = blockIdx.y;    // covers n in [nblk*128, nblk*128+128)

    // warp's B fragment base in g_Wfrag (chunk c, kstep k at: + c*2048 + k*512)
    const uint32_t* Wbase = g_Wfrag
        + ((size_t)(2 * nblk + nhalf) * NCHUNK) * 2048
        + (wnbit * 4) * 64 + lane * 2;

    // accumulators: 4 m-tiles x 4 n-tiles x 4 f32
    float C[4][4][4];
    #pragma unroll
    for (int mt = 0; mt < 4; mt++)
        #pragma unroll
        for (int nt = 0; nt < 4; nt++)
            #pragma unroll
            for (int r = 0; r < 4; r++) C[mt][nt][r] = 0.0f;

    // B double-buffered fragment registers, parity = global kstep & 1
    uint2 bfr[2][4];

    // A staging: 1024 cells (128 m x 8 j), 4 per thread
    const int aj = tid & 7;
    const int am = tid >> 3;         // 0..31
    float vA[4][4];

    auto LDB = [&](int c, int kstep, int p) {
        const uint32_t* src = Wbase + c * 2048 + kstep * 512;
        #pragma unroll
        for (int nt = 0; nt < 4; nt++)
            bfr[p][nt] = *(const uint2*)(src + nt * 64);   // coalesced LDG.64
    };

    auto LOADA = [&](int c) {
        #pragma unroll
        for (int t = 0; t < 4; t++) {
            const int m = am + 32 * t;
            const float* src = x + ((size_t)(bBase + m) * IN_DIM + (c * 8 + aj)) * MV;
            float4 lo = *(const float4*)src;
            vA[t][0] = lo.x; vA[t][1] = lo.y; vA[t][2] = lo.z; vA[t][3] = src[4];
        }
    };

    auto STOREA = [&](int buf) {
        uint32_t* SA = sm + buf * AF_WORDS;
        const int kstep = aj >> 1;
        const int jbit  = aj & 1;
        #pragma unroll
        for (int t = 0; t < 4; t++) {
            const int m      = am + 32 * t;
            const int wmm    = m >> 6;
            const int mt     = (m >> 4) & 3;
            const int rowbit = (m >> 3) & 1;
            const int r      = m & 7;
            uint32_t* p = SA + kstep * KSTRIDE + (wmm * 4 + mt) * 128
                             + (2 * jbit + rowbit) * 32 + 4 * r;
            uint4 val;
            val.x = f2tf32(vA[t][0]);
            val.y = f2tf32(vA[t][1]);
            val.z = f2tf32(vA[t][2]);
            val.w = f2tf32(vA[t][3]);
            *(uint4*)p = val;                  // STS.128, ~2-way
        }
    };

    LOADA(0);
    STOREA(0);
    LDB(0, 0, 0);                              // prime B pipeline (parity 0)
    __syncthreads();

    for (int c = 0; c < NCHUNK; c++) {
        const int buf = c & 1;
        if (c + 1 < NCHUNK) LOADA(c + 1);

        const uint32_t* SA = sm + buf * AF_WORDS;

        #pragma unroll
        for (int kstep = 0; kstep < 4; kstep++) {
            const int p = kstep & 1;
            // prefetch next kstep's B (crosses into chunk c+1 at kstep==3)
            if (!(kstep == 3 && c + 1 == NCHUNK)) {
                const int nc = (kstep == 3) ? c + 1 : c;
                LDB(nc, (kstep + 1) & 3, p ^ 1);
            }
            #pragma unroll
            for (int mt = 0; mt < 4; mt++) {
                const uint32_t* pa = SA + kstep * KSTRIDE + (wm * 4 + mt) * 128 + lane;
                uint4 a;
                a.x = pa[0];
                a.y = pa[32];
                a.z = pa[64];
                a.w = pa[96];
                #pragma unroll
                for (int nt = 0; nt < 4; nt++)
                    asm("mma.sync.aligned.m16n8k8.row.col.f32.tf32.tf32.f32 "
                        "{%0,%1,%2,%3}, {%4,%5,%6,%7}, {%8,%9}, {%0,%1,%2,%3};"
                        : "+f"(C[mt][nt][0]), "+f"(C[mt][nt][1]),
                          "+f"(C[mt][nt][2]), "+f"(C[mt][nt][3])
                        : "r"(a.x), "r"(a.y), "r"(a.z), "r"(a.w),
                          "r"(bfr[p][nt].x), "r"(bfr[p][nt].y));
            }
        }

        if (c + 1 < NCHUNK) STOREA(buf ^ 1);
        __syncthreads();
    }

    // ---- epilogue: C frags -> out; c0,c1 = (y0,y4) of i; rows +0/+8
    const int iBase = nblk * 64;
    #pragma unroll
    for (int nt = 0; nt < 4; nt++) {
        const int ig = iBase + wn * 16 + nt * 4 + (lane & 3);
        float4 blo = *(const float4*)(bias + (size_t)ig * MV);
        float4 bhi = *(const float4*)(bias + (size_t)ig * MV + 4);
        #pragma unroll
        for (int mt = 0; mt < 4; mt++) {
            #pragma unroll
            for (int h = 0; h < 2; h++) {
                const int brow = bBase + wm * 64 + mt * 16 + (lane >> 2) + 8 * h;
                float4 v0 = blo; v0.x += C[mt][nt][2 * h];
                float4 v1 = bhi; v1.x += C[mt][nt][2 * h + 1];
                float4* o = (float4*)(out + ((size_t)brow * OUT_DIM + ig) * MV);
                o[0] = v0;
                o[1] = v1;
            }
        }
    }
}

extern "C" void kernel_launch(void* const* d_in, const int* in_sizes, int n_in,
                              void* d_out, int out_size)
{
    const float* x    = (const float*)d_in[0];   // (8192, 256, 8)
    const float* w    = (const float*)d_in[1];   // (256, 256, 8)
    const float* bias = (const float*)d_in[2];   // (256, 8)
    float* out        = (float*)d_out;           // (8192, 256, 8)

    static int attr_set = 0;
    if (!attr_set) {
        cudaFuncSetAttribute(ga_gemm_kernel, cudaFuncAttributeMaxDynamicSharedMemorySize,
                             SM_BYTES);
        attr_set = 1;
    }

    wprep_kernel<<<(NNDIM * KDIM) / 256, 256>>>(w);
    dim3 grid(B_DIM / BM, NNDIM / BN);           // (64, 4) = 256 CTAs
    ga_gemm_kernel<<<grid, NTHR, SM_BYTES>>>(x, bias, out);
}